// round 14
// baseline (speedup 1.0000x reference)
#include <cuda_runtime.h>
#include <cuda_fp16.h>
#include <cstdint>

#define HW     56
#define CIN    128
#define COUT   128
#define NB     5
#define WELEMS (COUT * CIN * 9)

// ---------------- device scratch (no allocs allowed) ----------------
__device__ float g_part[40];
// effective weights, fp16, pre-swizzled ldmatrix-ready tiles:
// [tap][chunk][k=64][n=128] ; byte off within tile = k*256 + ((n*2)^((k&7)*16))
__device__ __align__(256) __half g_wB[9 * 2 * 64 * 128];

// ---------------- helpers ----------------
static __device__ __forceinline__ uint32_t smem_u32(const void* p) {
    uint32_t a;
    asm("{ .reg .u64 t; cvta.to.shared.u64 t, %1; cvt.u32.u64 %0, t; }" : "=r"(a) : "l"(p));
    return a;
}

static __device__ __forceinline__ void mma16816(float* c, const uint32_t* a,
                                                uint32_t b0, uint32_t b1) {
    asm volatile(
        "mma.sync.aligned.m16n8k16.row.col.f32.f16.f16.f32 "
        "{%0,%1,%2,%3}, {%4,%5,%6,%7}, {%8,%9}, {%0,%1,%2,%3};"
        : "+f"(c[0]), "+f"(c[1]), "+f"(c[2]), "+f"(c[3])
        : "r"(a[0]), "r"(a[1]), "r"(a[2]), "r"(a[3]), "r"(b0), "r"(b1));
}

static __device__ __forceinline__ void ldsm4t(uint32_t* r, uint32_t addr) {
    asm volatile("ldmatrix.sync.aligned.m8n8.x4.trans.shared.b16 {%0,%1,%2,%3}, [%4];"
                 : "=r"(r[0]), "=r"(r[1]), "=r"(r[2]), "=r"(r[3])
                 : "r"(addr));
}

// ============ prep 1: partial sums of |w| (40 blocks, float4) ============
__global__ void mean_abs_part_kernel(const float* __restrict__ w) {
    int n = blockIdx.x >> 3, seg = blockIdx.x & 7;
    const float4* wn = (const float4*)(w + (size_t)n * WELEMS + seg * (WELEMS / 8));
    float s = 0.f;
#pragma unroll 2
    for (int i = threadIdx.x; i < WELEMS / 32; i += 256) {
        float4 f = __ldg(&wn[i]);
        s += fabsf(f.x) + fabsf(f.y) + fabsf(f.z) + fabsf(f.w);
    }
    __shared__ float red[256];
    red[threadIdx.x] = s;
    __syncthreads();
    for (int off = 128; off > 0; off >>= 1) {
        if (threadIdx.x < off) red[threadIdx.x] += red[threadIdx.x + off];
        __syncthreads();
    }
    if (threadIdx.x == 0) g_part[blockIdx.x] = red[0];
}

// ====== prep 2: effective weight -> swizzled fp16 B tiles ======
// one thread per (o,i): reads 9 contiguous taps per base (coalesced 1152B/warp)
__global__ void build_wB_kernel(const float* __restrict__ w,
                                const float* __restrict__ scales) {
    int idx = blockIdx.x * 256 + threadIdx.x;   // o*128 + i, [0,16384)
    float m[NB];
#pragma unroll
    for (int n = 0; n < NB; n++) {
        float s = 0.f;
#pragma unroll
        for (int j = 0; j < 8; j++) s += __ldg(&g_part[n * 8 + j]);
        m[n] = s / (float)WELEMS;
    }
    int o = idx >> 7;
    int i = idx & 127;
    float v[9];
#pragma unroll
    for (int j = 0; j < 9; j++) v[j] = 0.f;
#pragma unroll
    for (int n = 0; n < NB; n++) {
        const float* wp = w + (((size_t)n * COUT + o) * CIN + i) * 9;
        float sm = __ldg(&scales[n]) * m[n];
#pragma unroll
        for (int j = 0; j < 9; j++) {
            float wv = __ldg(&wp[j]);
            float sg = (wv > 0.f) ? 1.f : ((wv < 0.f) ? -1.f : 0.f);
            v[j] += sm * sg;
        }
    }
    int chunk = i >> 6;
    int kl = i & 63;
    uint32_t boff = (uint32_t)kl * 256 + (((uint32_t)o * 2) ^ (((uint32_t)kl & 7) * 16));
#pragma unroll
    for (int kidx = 0; kidx < 9; kidx++) {
        size_t tile = (size_t)(kidx * 2 + chunk) * 8192;
        g_wB[tile + (boff >> 1)] = __float2half_rn(v[kidx]);
    }
}

// === conv kernel: HMMA implicit GEMM, 512 thr, 4-buf B pipe, pipelined frags ===
// dyn smem (bytes):
//   [0]      B tiles: 4 bufs x 16384 = 65536
//   [65536]  slab: 32 k-pair rows x 232 words + 16 pad = 7456 words = 29824
#define SM_B       0u
#define SM_SLAB    65536u
#define SMEM_TOTAL (65536 + 7456 * 4)   // 95360

static __device__ __forceinline__ void issue_B(uint32_t sdst, const uint8_t* gsrc, int tid) {
    uint32_t s = sdst + (uint32_t)tid * 32u;
    const uint8_t* g = gsrc + tid * 32;
    asm volatile("cp.async.cg.shared.global [%0], [%1], 16;" :: "r"(s), "l"(g));
    asm volatile("cp.async.cg.shared.global [%0], [%1], 16;" :: "r"(s + 16u), "l"(g + 16));
    asm volatile("cp.async.commit_group;" ::: "memory");
}

__global__ void __launch_bounds__(512, 2)
conv_kernel(const float* __restrict__ x, float* __restrict__ out) {
    extern __shared__ __align__(16) uint8_t smem[];
    const uint32_t sb = smem_u32(smem);
    uint32_t* slabh = (uint32_t*)(smem + SM_SLAB);

    const int tid = threadIdx.x;
    const int lane = tid & 31, wid = tid >> 5;
    const int g = lane >> 2, tig = lane & 3;
    const int mw = wid & 7;          // m block of 16  (8 blocks -> M=128)
    const int nw = wid >> 3;         // n half of 64   (2 halves -> N=128)
    const int mf = mw * 16;
    const int r0 = blockIdx.x * 2;   // first output row
    const int b = blockIdx.y;

    // zero slab pad (finite garbage only)
    if (tid < 16) slabh[7440 + tid] = 0;

    float acc[8][4];
#pragma unroll
    for (int j = 0; j < 8; j++)
#pragma unroll
        for (int q = 0; q < 4; q++) acc[j][q] = 0.f;

    // B ldmatrix lane constants — swizzle offsets are s-invariant up to +s*4096
    const int krow_l = (lane & 7) + ((lane & 8) ? 8 : 0);
    const int nsel = ((lane & 16) ? 8 : 0) + nw * 64;
    uint32_t bnp[4];
#pragma unroll
    for (int np = 0; np < 4; np++)
        bnp[np] = (uint32_t)krow_l * 256u +
                  ((((uint32_t)(nsel + np * 16)) * 2u) ^ (((uint32_t)krow_l & 7u) * 16u));

    // pre-issue B tiles for iters 0 and 1 (tap0/ch0, tap1/ch0)
    issue_B(sb + SM_B, (const uint8_t*)g_wB, tid);
    issue_B(sb + SM_B + 16384u, (const uint8_t*)g_wB + 2 * 16384, tid);

#pragma unroll 1
    for (int iter = 0; iter < 18; iter++) {
        const int chunk = (iter >= 9) ? 1 : 0;
        const int kidx = iter - 9 * chunk;
        const int ky = kidx / 3;
        const int kx = kidx - 3 * ky;

        if ((iter & 1) == 0) {
            // one block-wide ordering point per 2 iters
            __syncthreads();
            if (iter + 2 < 18) {
                int n2 = iter + 2;
                int nc2 = (n2 >= 9) ? 1 : 0;
                int nk2 = n2 - 9 * nc2;
                issue_B(sb + SM_B + (uint32_t)((n2 & 3) * 16384),
                        (const uint8_t*)g_wB + (size_t)(nk2 * 2 + nc2) * 16384, tid);
                if (iter + 3 < 18) {
                    int n3 = iter + 3;
                    int nc3 = (n3 >= 9) ? 1 : 0;
                    int nk3 = n3 - 9 * nc3;
                    issue_B(sb + SM_B + (uint32_t)((n3 & 3) * 16384),
                            (const uint8_t*)g_wB + (size_t)(nk3 * 2 + nc3) * 16384, tid);
                    asm volatile("cp.async.wait_group 2;" ::: "memory");
                } else {
                    asm volatile("cp.async.wait_group 1;" ::: "memory");
                }
            } else {
                asm volatile("cp.async.wait_group 0;" ::: "memory");
            }
        }

        // stage x slab for this 64-channel chunk (coalesced; pad = 1.0)
        if (kidx == 0) {
            if (iter == 9) __syncthreads();   // all warps done reading chunk-0 slab
            const float* xp = x + ((size_t)b * CIN + chunk * 64) * (HW * HW);
#pragma unroll 1
            for (int idx = tid; idx < 64 * 232; idx += 512) {
                int ch = idx / 232;
                int pos = idx - ch * 232;
                int r = pos / 58;
                int c = pos - r * 58;
                int gy = r0 - 1 + r, gx = c - 1;
                float v = 1.0f;
                if ((unsigned)gy < HW && (unsigned)gx < HW)
                    v = __ldg(xp + ch * (HW * HW) + gy * HW + gx);
                int wd = (ch >> 1) * 232 + pos;
                ((__half*)slabh)[wd * 2 + (ch & 1)] = __float2half_rn(v);
            }
            __syncthreads();                  // slab visible before compute
        }

        const uint32_t cur = sb + SM_B + (uint32_t)((iter & 3) * 16384);
        const int pos0 = ((mf >> 6) + ky) * 58 + (mf & 63) + kx + g;

        // ---- software-pipelined fragment loop ----
        uint32_t ah[4], an[4];
        {   // preload A for s=0
            const int w0 = tig * 232 + pos0;
            ah[0] = slabh[w0];
            ah[1] = slabh[w0 + 8];
            ah[2] = slabh[w0 + 4 * 232];
            ah[3] = slabh[w0 + 4 * 232 + 8];
        }
#pragma unroll
        for (int s = 0; s < 4; s++) {
            const uint32_t sbb = cur + (uint32_t)(s * 4096);
            uint32_t bh[4], bn[4];
            ldsm4t(bh, sbb + bnp[0]);                 // B for np=0
            if (s < 3) {                              // prefetch A for s+1
                const int w1 = ((s + 1) * 8 + tig) * 232 + pos0;
                an[0] = slabh[w1];
                an[1] = slabh[w1 + 8];
                an[2] = slabh[w1 + 4 * 232];
                an[3] = slabh[w1 + 4 * 232 + 8];
            }
#pragma unroll
            for (int np = 0; np < 4; np++) {
                if (np < 3) ldsm4t(bn, sbb + bnp[np + 1]);  // prefetch B for np+1
                mma16816(acc[np * 2],     ah, bh[0], bh[1]);
                mma16816(acc[np * 2 + 1], ah, bh[2], bh[3]);
                if (np < 3) {
                    bh[0] = bn[0]; bh[1] = bn[1]; bh[2] = bn[2]; bh[3] = bn[3];
                }
            }
            if (s < 3) {
                ah[0] = an[0]; ah[1] = an[1]; ah[2] = an[2]; ah[3] = an[3];
            }
        }
    }

    // ---- epilogue: register accumulators -> gmem ----
    {
        const int y = r0 + (mf >> 6);
        const int xa = (mf & 63) + g;     // <= 55, always valid
        const int xb = xa + 8;
#pragma unroll
        for (int ni = 0; ni < 8; ni++) {
            const int n = nw * 64 + ni * 8 + tig * 2;
            float* p = out + ((size_t)b * COUT + n) * (HW * HW) + y * HW;
            p[xa] = acc[ni][0];
            p[HW * HW + xa] = acc[ni][1];
            if (xb < HW) {
                p[xb] = acc[ni][2];
                p[HW * HW + xb] = acc[ni][3];
            }
        }
    }
}

// ================= launcher =================
extern "C" void kernel_launch(void* const* d_in, const int* in_sizes, int n_in,
                              void* d_out, int out_size) {
    const float* x = (const float*)d_in[0];        // [32,128,56,56]
    const float* w = (const float*)d_in[1];        // [5,128,128,3,3]
    const float* scales = (const float*)d_in[2];   // [5]
    float* out = (float*)d_out;                    // [32,128,56,56]

    cudaFuncSetAttribute(conv_kernel, cudaFuncAttributeMaxDynamicSharedMemorySize,
                         SMEM_TOTAL);

    mean_abs_part_kernel<<<40, 256>>>(w);
    build_wB_kernel<<<64, 256>>>(w, scales);
    conv_kernel<<<dim3(28, 32), 512, SMEM_TOTAL>>>(x, out);
}

// round 15
// speedup vs baseline: 1.0187x; 1.0187x over previous
#include <cuda_runtime.h>
#include <cuda_fp16.h>
#include <cstdint>

#define HW     56
#define CIN    128
#define COUT   128
#define NB     5
#define WELEMS (COUT * CIN * 9)

// ---------------- device scratch (no allocs allowed) ----------------
__device__ float g_part[80];
// effective weights, fp16, pre-swizzled ldmatrix-ready tiles:
// [tap][chunk][k=64][n=128] ; byte off within tile = k*256 + ((n*2)^((k&7)*16))
__device__ __align__(256) __half g_wB[9 * 2 * 64 * 128];

// ---------------- helpers ----------------
static __device__ __forceinline__ uint32_t smem_u32(const void* p) {
    uint32_t a;
    asm("{ .reg .u64 t; cvta.to.shared.u64 t, %1; cvt.u32.u64 %0, t; }" : "=r"(a) : "l"(p));
    return a;
}

static __device__ __forceinline__ void mma16816(float* c, const uint32_t* a,
                                                uint32_t b0, uint32_t b1) {
    asm volatile(
        "mma.sync.aligned.m16n8k16.row.col.f32.f16.f16.f32 "
        "{%0,%1,%2,%3}, {%4,%5,%6,%7}, {%8,%9}, {%0,%1,%2,%3};"
        : "+f"(c[0]), "+f"(c[1]), "+f"(c[2]), "+f"(c[3])
        : "r"(a[0]), "r"(a[1]), "r"(a[2]), "r"(a[3]), "r"(b0), "r"(b1));
}

static __device__ __forceinline__ void ldsm4t(uint32_t* r, uint32_t addr) {
    asm volatile("ldmatrix.sync.aligned.m8n8.x4.trans.shared.b16 {%0,%1,%2,%3}, [%4];"
                 : "=r"(r[0]), "=r"(r[1]), "=r"(r[2]), "=r"(r[3])
                 : "r"(addr));
}

// ====== prep 1: partial sums of |w| (80 blocks = 5 bases x 16 segs, float4) ======
__global__ void mean_abs_part_kernel(const float* __restrict__ w) {
    int n = blockIdx.x >> 4, seg = blockIdx.x & 15;
    const float4* wn = (const float4*)(w + (size_t)n * WELEMS + seg * (WELEMS / 16));
    float s = 0.f;
#pragma unroll 4
    for (int i = threadIdx.x; i < WELEMS / 64; i += 256) {
        float4 f = __ldg(&wn[i]);
        s += fabsf(f.x) + fabsf(f.y) + fabsf(f.z) + fabsf(f.w);
    }
    __shared__ float red[256];
    red[threadIdx.x] = s;
    __syncthreads();
    for (int off = 128; off > 0; off >>= 1) {
        if (threadIdx.x < off) red[threadIdx.x] += red[threadIdx.x + off];
        __syncthreads();
    }
    if (threadIdx.x == 0) g_part[blockIdx.x] = red[0];
}

// ====== prep 2: effective weight -> swizzled fp16 B tiles ======
// one thread per (o-pair, i): coalesced reads; paired uint32 (o,o+1) writes
__global__ void build_wB_kernel(const float* __restrict__ w,
                                const float* __restrict__ scales) {
    int idx = blockIdx.x * 256 + threadIdx.x;   // op*128 + i, [0,8192)
    float m[NB];
#pragma unroll
    for (int n = 0; n < NB; n++) {
        float s = 0.f;
#pragma unroll
        for (int j = 0; j < 16; j++) s += __ldg(&g_part[n * 16 + j]);
        m[n] = s / (float)WELEMS;
    }
    int op = idx >> 7;            // o-pair 0..63
    int i = idx & 127;            // cin
    int o0 = op * 2;
    float v0[9], v1[9];
#pragma unroll
    for (int j = 0; j < 9; j++) { v0[j] = 0.f; v1[j] = 0.f; }
#pragma unroll
    for (int n = 0; n < NB; n++) {
        const float* wp0 = w + (((size_t)n * COUT + o0) * CIN + i) * 9;
        const float* wp1 = wp0 + (size_t)CIN * 9;
        float sm = __ldg(&scales[n]) * m[n];
#pragma unroll
        for (int j = 0; j < 9; j++) {
            float w0 = __ldg(&wp0[j]);
            float w1 = __ldg(&wp1[j]);
            v0[j] += sm * ((w0 > 0.f) ? 1.f : ((w0 < 0.f) ? -1.f : 0.f));
            v1[j] += sm * ((w1 > 0.f) ? 1.f : ((w1 < 0.f) ? -1.f : 0.f));
        }
    }
    int chunk = i >> 6;
    int kl = i & 63;
    // byte offset of (kl, o0); o0 even -> o0,o0+1 share one aligned uint32
    uint32_t boff = (uint32_t)kl * 256 + (((uint32_t)o0 * 2) ^ (((uint32_t)kl & 7) * 16));
    uint32_t* wB32 = (uint32_t*)g_wB;
#pragma unroll
    for (int kidx = 0; kidx < 9; kidx++) {
        size_t tile = (size_t)(kidx * 2 + chunk) * 8192;   // in halves
        __half h0 = __float2half_rn(v0[kidx]);
        __half h1 = __float2half_rn(v1[kidx]);
        uint32_t pk = (uint32_t)__half_as_ushort(h0) |
                      ((uint32_t)__half_as_ushort(h1) << 16);
        wB32[(tile + (boff >> 1)) >> 1] = pk;
    }
}

// === conv kernel: HMMA implicit GEMM, 512 thr, 4-buf B pipe, sync per 2 iters ===
// (byte-identical to the 173.4us R13 kernel)
// dyn smem (bytes):
//   [0]      B tiles: 4 bufs x 16384 = 65536
//   [65536]  slab: 32 k-pair rows x 232 words + 16 pad = 7456 words = 29824
#define SM_B       0u
#define SM_SLAB    65536u
#define SMEM_TOTAL (65536 + 7456 * 4)   // 95360

static __device__ __forceinline__ void issue_B(uint32_t sdst, const uint8_t* gsrc, int tid) {
    uint32_t s = sdst + (uint32_t)tid * 32u;
    const uint8_t* g = gsrc + tid * 32;
    asm volatile("cp.async.cg.shared.global [%0], [%1], 16;" :: "r"(s), "l"(g));
    asm volatile("cp.async.cg.shared.global [%0], [%1], 16;" :: "r"(s + 16u), "l"(g + 16));
    asm volatile("cp.async.commit_group;" ::: "memory");
}

__global__ void __launch_bounds__(512, 2)
conv_kernel(const float* __restrict__ x, float* __restrict__ out) {
    extern __shared__ __align__(16) uint8_t smem[];
    const uint32_t sb = smem_u32(smem);
    uint32_t* slabh = (uint32_t*)(smem + SM_SLAB);

    const int tid = threadIdx.x;
    const int lane = tid & 31, wid = tid >> 5;
    const int g = lane >> 2, tig = lane & 3;
    const int mw = wid & 7;          // m block of 16  (8 blocks -> M=128)
    const int nw = wid >> 3;         // n half of 64   (2 halves -> N=128)
    const int mf = mw * 16;
    const int r0 = blockIdx.x * 2;   // first output row
    const int b = blockIdx.y;

    // zero slab pad (finite garbage only)
    if (tid < 16) slabh[7440 + tid] = 0;

    float acc[8][4];
#pragma unroll
    for (int j = 0; j < 8; j++)
#pragma unroll
        for (int q = 0; q < 4; q++) acc[j][q] = 0.f;

    // B ldmatrix lane constants — swizzle offsets are s-invariant up to +s*4096
    const int krow_l = (lane & 7) + ((lane & 8) ? 8 : 0);
    const int nsel = ((lane & 16) ? 8 : 0) + nw * 64;
    uint32_t bnp[4];
#pragma unroll
    for (int np = 0; np < 4; np++)
        bnp[np] = (uint32_t)krow_l * 256u +
                  ((((uint32_t)(nsel + np * 16)) * 2u) ^ (((uint32_t)krow_l & 7u) * 16u));

    // pre-issue B tiles for iters 0 and 1 (tap0/ch0, tap1/ch0)
    issue_B(sb + SM_B, (const uint8_t*)g_wB, tid);
    issue_B(sb + SM_B + 16384u, (const uint8_t*)g_wB + 2 * 16384, tid);

#pragma unroll 1
    for (int iter = 0; iter < 18; iter++) {
        const int chunk = (iter >= 9) ? 1 : 0;
        const int kidx = iter - 9 * chunk;
        const int ky = kidx / 3;
        const int kx = kidx - 3 * ky;

        if ((iter & 1) == 0) {
            // one block-wide ordering point per 2 iters
            __syncthreads();
            if (iter + 2 < 18) {
                int n2 = iter + 2;
                int nc2 = (n2 >= 9) ? 1 : 0;
                int nk2 = n2 - 9 * nc2;
                issue_B(sb + SM_B + (uint32_t)((n2 & 3) * 16384),
                        (const uint8_t*)g_wB + (size_t)(nk2 * 2 + nc2) * 16384, tid);
                if (iter + 3 < 18) {
                    int n3 = iter + 3;
                    int nc3 = (n3 >= 9) ? 1 : 0;
                    int nk3 = n3 - 9 * nc3;
                    issue_B(sb + SM_B + (uint32_t)((n3 & 3) * 16384),
                            (const uint8_t*)g_wB + (size_t)(nk3 * 2 + nc3) * 16384, tid);
                    asm volatile("cp.async.wait_group 2;" ::: "memory");
                } else {
                    asm volatile("cp.async.wait_group 1;" ::: "memory");
                }
            } else {
                asm volatile("cp.async.wait_group 0;" ::: "memory");
            }
        }

        // stage x slab for this 64-channel chunk (coalesced; pad = 1.0)
        if (kidx == 0) {
            if (iter == 9) __syncthreads();   // all warps done reading chunk-0 slab
            const float* xp = x + ((size_t)b * CIN + chunk * 64) * (HW * HW);
#pragma unroll 1
            for (int idx = tid; idx < 64 * 232; idx += 512) {
                int ch = idx / 232;
                int pos = idx - ch * 232;
                int r = pos / 58;
                int c = pos - r * 58;
                int gy = r0 - 1 + r, gx = c - 1;
                float v = 1.0f;
                if ((unsigned)gy < HW && (unsigned)gx < HW)
                    v = __ldg(xp + ch * (HW * HW) + gy * HW + gx);
                int wd = (ch >> 1) * 232 + pos;
                ((__half*)slabh)[wd * 2 + (ch & 1)] = __float2half_rn(v);
            }
            __syncthreads();                  // slab visible before compute
        }

        const uint32_t cur = sb + SM_B + (uint32_t)((iter & 3) * 16384);
#pragma unroll
        for (int s = 0; s < 4; s++) {
            // ---- A fragment via plain LDS.32 from k-pair-packed slab ----
            const int pos0 = ((mf >> 6) + ky) * 58 + (mf & 63) + kx + g;
            const int w0 = (s * 8 + tig) * 232 + pos0;
            uint32_t ah[4];
            ah[0] = slabh[w0];
            ah[1] = slabh[w0 + 8];
            ah[2] = slabh[w0 + 4 * 232];
            ah[3] = slabh[w0 + 4 * 232 + 8];

            const uint32_t sbb = cur + (uint32_t)(s * 4096);
#pragma unroll
            for (int np = 0; np < 4; np++) {
                uint32_t bh[4];
                ldsm4t(bh, sbb + bnp[np]);
                mma16816(acc[np * 2],     ah, bh[0], bh[1]);
                mma16816(acc[np * 2 + 1], ah, bh[2], bh[3]);
            }
        }
    }

    // ---- epilogue: register accumulators -> gmem ----
    {
        const int y = r0 + (mf >> 6);
        const int xa = (mf & 63) + g;     // <= 55, always valid
        const int xb = xa + 8;
#pragma unroll
        for (int ni = 0; ni < 8; ni++) {
            const int n = nw * 64 + ni * 8 + tig * 2;
            float* p = out + ((size_t)b * COUT + n) * (HW * HW) + y * HW;
            p[xa] = acc[ni][0];
            p[HW * HW + xa] = acc[ni][1];
            if (xb < HW) {
                p[xb] = acc[ni][2];
                p[HW * HW + xb] = acc[ni][3];
            }
        }
    }
}

// ================= launcher =================
extern "C" void kernel_launch(void* const* d_in, const int* in_sizes, int n_in,
                              void* d_out, int out_size) {
    const float* x = (const float*)d_in[0];        // [32,128,56,56]
    const float* w = (const float*)d_in[1];        // [5,128,128,3,3]
    const float* scales = (const float*)d_in[2];   // [5]
    float* out = (float*)d_out;                    // [32,128,56,56]

    cudaFuncSetAttribute(conv_kernel, cudaFuncAttributeMaxDynamicSharedMemorySize,
                         SMEM_TOTAL);

    mean_abs_part_kernel<<<80, 256>>>(w);
    build_wB_kernel<<<32, 256>>>(w, scales);
    conv_kernel<<<dim3(28, 32), 512, SMEM_TOTAL>>>(x, out);
}